// round 2
// baseline (speedup 1.0000x reference)
#include <cuda_runtime.h>
#include <mma.h>
#include <math.h>

using namespace nvcuda;

#define BATCH 4
#define SEQ   2048
#define CH    2048
#define NH    16
#define HD    128
#define QKV_N 6144

// ---------------- scratch (no allocs allowed -> __device__ globals) ----------
__device__ float g_qkv[(size_t)BATCH * SEQ * QKV_N];       // 201 MB
__device__ float g_q[(size_t)BATCH * NH * SEQ * HD];       // 67 MB
__device__ float g_k[(size_t)BATCH * NH * SEQ * HD];
__device__ float g_v[(size_t)BATCH * NH * SEQ * HD];
__device__ float g_o[(size_t)BATCH * NH * SEQ * HD];
__device__ float g_attn[(size_t)BATCH * SEQ * CH];         // 67 MB

// ---------------- generic TF32 GEMM: C[M,N] = A[M,K] @ B[N,K]^T --------------
#define BM 128
#define BN 64
#define BK 32
#define LDA 36
#define LDB 36

__global__ __launch_bounds__(256) void gemm_tf32(
    const float* __restrict__ A, const float* __restrict__ Bm,
    float* __restrict__ C, int M, int N, int K)
{
    __shared__ float As[BM * LDA];
    __shared__ float Bs[BN * LDB];

    int tid = threadIdx.x;
    int wid = tid >> 5;
    int wr  = wid & 3;    // warp row block (32 rows each)
    int wc  = wid >> 2;   // warp col block (32 cols each)
    int bm  = blockIdx.y * BM;
    int bn  = blockIdx.x * BN;

    wmma::fragment<wmma::accumulator, 16, 16, 8, float> acc[2][2];
    #pragma unroll
    for (int i = 0; i < 2; i++)
        #pragma unroll
        for (int j = 0; j < 2; j++) wmma::fill_fragment(acc[i][j], 0.0f);

    for (int k0 = 0; k0 < K; k0 += BK) {
        // A tile: 128x32 -> 1024 float4, 4 per thread
        #pragma unroll
        for (int r = 0; r < 4; r++) {
            int idx = tid + r * 256;
            int row = idx >> 3;
            int c4  = idx & 7;
            float4 v = *(const float4*)(A + (size_t)(bm + row) * K + k0 + c4 * 4);
            *(float4*)(As + row * LDA + c4 * 4) = v;
        }
        // B tile: 64x32 -> 512 float4, 2 per thread
        #pragma unroll
        for (int r = 0; r < 2; r++) {
            int idx = tid + r * 256;
            int row = idx >> 3;
            int c4  = idx & 7;
            float4 v = *(const float4*)(Bm + (size_t)(bn + row) * K + k0 + c4 * 4);
            *(float4*)(Bs + row * LDB + c4 * 4) = v;
        }
        __syncthreads();

        #pragma unroll
        for (int kk = 0; kk < BK; kk += 8) {
            wmma::fragment<wmma::matrix_a, 16, 16, 8, wmma::precision::tf32, wmma::row_major> a[2];
            wmma::fragment<wmma::matrix_b, 16, 16, 8, wmma::precision::tf32, wmma::col_major> b[2];
            #pragma unroll
            for (int i = 0; i < 2; i++) {
                wmma::load_matrix_sync(a[i], As + (wr * 32 + i * 16) * LDA + kk, LDA);
                #pragma unroll
                for (int e = 0; e < a[i].num_elements; e++)
                    a[i].x[e] = wmma::__float_to_tf32(a[i].x[e]);
                wmma::load_matrix_sync(b[i], Bs + (wc * 32 + i * 16) * LDB + kk, LDB);
                #pragma unroll
                for (int e = 0; e < b[i].num_elements; e++)
                    b[i].x[e] = wmma::__float_to_tf32(b[i].x[e]);
            }
            #pragma unroll
            for (int i = 0; i < 2; i++)
                #pragma unroll
                for (int j = 0; j < 2; j++)
                    wmma::mma_sync(acc[i][j], a[i], b[j], acc[i][j]);
        }
        __syncthreads();
    }

    #pragma unroll
    for (int i = 0; i < 2; i++)
        #pragma unroll
        for (int j = 0; j < 2; j++)
            wmma::store_matrix_sync(
                C + (size_t)(bm + wr * 32 + i * 16) * N + bn + wc * 32 + j * 16,
                acc[i][j], N, wmma::mem_row_major);
}

// ------------- bias + RoPE + split into [B,H,T,D] q/k/v ----------------------
__global__ __launch_bounds__(256) void rope_split(const float* __restrict__ bias)
{
    int token = blockIdx.x;              // b*SEQ + t
    int b = token >> 11;                 // /2048
    int t = token & 2047;
    const float2* row = (const float2*)(g_qkv + (size_t)token * QKV_N);
    const float2* bq  = (const float2*)bias;
    int tid = threadIdx.x;

    const float L2B_OVER_HALF = 13.287712379549449f / 64.0f;  // log2(10000)/64

    // q and k: 1024 rotation pairs each
    for (int p = tid; p < 1024; p += 256) {
        int h = p >> 6;
        int i = p & 63;
        float theta = exp2f(-(float)i * L2B_OVER_HALF);
        float ang = (float)t * theta;
        float s, c;
        sincosf(ang, &s, &c);

        size_t dst = ((size_t)(b * NH + h) * SEQ + t) * 64 + i;

        float2 xq = row[p];
        float2 bb = bq[p];
        float x1 = xq.x + bb.x, x2 = xq.y + bb.y;
        float2 oq;
        oq.x = x1 * c - x2 * s;
        oq.y = x1 * s + x2 * c;
        ((float2*)g_q)[dst] = oq;

        float2 xk = row[1024 + p];
        float2 bk = bq[1024 + p];
        float k1 = xk.x + bk.x, k2 = xk.y + bk.y;
        float2 ok;
        ok.x = k1 * c - k2 * s;
        ok.y = k1 * s + k2 * c;
        ((float2*)g_k)[dst] = ok;
    }
    // v: copy + bias
    for (int p = tid; p < 1024; p += 256) {
        int h = p >> 6;
        int i = p & 63;
        float2 xv = row[2048 + p];
        float2 bv = bq[2048 + p];
        float2 ov;
        ov.x = xv.x + bv.x;
        ov.y = xv.y + bv.y;
        ((float2*)g_v)[((size_t)(b * NH + h) * SEQ + t) * 64 + i] = ov;
    }
}

// ------------------------- flash attention -----------------------------------
#define BR 64
#define BC 64
#define LQT 132   // ld for Q/K/V/O tiles
#define LST 68    // ld for S tile
// smem floats: Q 8448, K 8448, V 8448, O 8448, S 4352, m 64, l 64
#define FLASH_SMEM_FLOATS (8448*4 + 4352 + 128)

__global__ __launch_bounds__(256) void flash_attn()
{
    extern __shared__ float sm[];
    float* Qs = sm;
    float* Ks = sm + 8448;
    float* Vs = sm + 16896;
    float* Os = sm + 25344;
    float* Ss = sm + 33792;
    float* mrow = sm + 38144;
    float* lrow = sm + 38208;

    int qt = blockIdx.x, h = blockIdx.y, b = blockIdx.z;
    int tid = threadIdx.x;
    int wid = tid >> 5;
    int wr = wid & 3;
    int wc = wid >> 2;

    const float* Qg = g_q + ((size_t)(b * NH + h) * SEQ + qt * BR) * HD;
    const float* Kg = g_k + (size_t)(b * NH + h) * SEQ * HD;
    const float* Vg = g_v + (size_t)(b * NH + h) * SEQ * HD;
    float*       Og = g_o + ((size_t)(b * NH + h) * SEQ + qt * BR) * HD;

    // load Q tile, init O/m/l
    #pragma unroll
    for (int r = 0; r < 8; r++) {
        int idx = tid + r * 256;
        int row = idx >> 5;
        int c4  = idx & 31;
        *(float4*)(Qs + row * LQT + c4 * 4) = *(const float4*)(Qg + row * HD + c4 * 4);
        *(float4*)(Os + row * LQT + c4 * 4) = make_float4(0.f, 0.f, 0.f, 0.f);
    }
    if (tid < 64) { mrow[tid] = -1e30f; lrow[tid] = 0.0f; }
    __syncthreads();

    const float scale = 0.08838834764831845f;  // 1/sqrt(128)

    for (int kt = 0; kt <= qt; kt++) {
        // load K and V tiles
        #pragma unroll
        for (int r = 0; r < 8; r++) {
            int idx = tid + r * 256;
            int row = idx >> 5;
            int c4  = idx & 31;
            *(float4*)(Ks + row * LQT + c4 * 4) =
                *(const float4*)(Kg + (size_t)(kt * BC + row) * HD + c4 * 4);
            *(float4*)(Vs + row * LQT + c4 * 4) =
                *(const float4*)(Vg + (size_t)(kt * BC + row) * HD + c4 * 4);
        }
        __syncthreads();

        // S = Q @ K^T  (64x64, K-dim 128)
        {
            wmma::fragment<wmma::accumulator, 16, 16, 8, float> sacc[2];
            wmma::fill_fragment(sacc[0], 0.0f);
            wmma::fill_fragment(sacc[1], 0.0f);
            #pragma unroll
            for (int kk = 0; kk < HD; kk += 8) {
                wmma::fragment<wmma::matrix_a, 16, 16, 8, wmma::precision::tf32, wmma::row_major> a;
                wmma::load_matrix_sync(a, Qs + (wr * 16) * LQT + kk, LQT);
                #pragma unroll
                for (int e = 0; e < a.num_elements; e++) a.x[e] = wmma::__float_to_tf32(a.x[e]);
                #pragma unroll
                for (int j = 0; j < 2; j++) {
                    wmma::fragment<wmma::matrix_b, 16, 16, 8, wmma::precision::tf32, wmma::col_major> bfr;
                    wmma::load_matrix_sync(bfr, Ks + (wc * 32 + j * 16) * LQT + kk, LQT);
                    #pragma unroll
                    for (int e = 0; e < bfr.num_elements; e++) bfr.x[e] = wmma::__float_to_tf32(bfr.x[e]);
                    wmma::mma_sync(sacc[j], a, bfr, sacc[j]);
                }
            }
            #pragma unroll
            for (int j = 0; j < 2; j++)
                wmma::store_matrix_sync(Ss + (wr * 16) * LST + wc * 32 + j * 16,
                                        sacc[j], LST, wmma::mem_row_major);
        }
        __syncthreads();

        // online softmax (4 threads per row)
        {
            int i   = tid >> 2;
            int sub = tid & 3;
            int gq  = qt * BR + i;
            float* srow = Ss + i * LST;

            float vals[16];
            float mx = -1e30f;
            #pragma unroll
            for (int jj = 0; jj < 16; jj++) {
                int j  = sub + jj * 4;
                int gk = kt * BC + j;
                float sv = (gk <= gq) ? srow[j] * scale : -1e30f;
                vals[jj] = sv;
                mx = fmaxf(mx, sv);
            }
            mx = fmaxf(mx, __shfl_xor_sync(0xffffffffu, mx, 1));
            mx = fmaxf(mx, __shfl_xor_sync(0xffffffffu, mx, 2));

            float mold = mrow[i];            // all 4 lanes read
            float mnew = fmaxf(mold, mx);
            float sum = 0.0f;
            #pragma unroll
            for (int jj = 0; jj < 16; jj++) {
                float p = __expf(vals[jj] - mnew);
                sum += p;
                srow[sub + jj * 4] = p;
            }
            sum += __shfl_xor_sync(0xffffffffu, sum, 1);
            sum += __shfl_xor_sync(0xffffffffu, sum, 2);

            __syncwarp();                    // order reads of mrow before the write
            float alpha = __expf(mold - mnew);
            if (sub == 0) {
                mrow[i] = mnew;
                lrow[i] = lrow[i] * alpha + sum;
            }
            // rescale O row
            float* orow = Os + i * LQT + sub * 32;
            if (alpha != 1.0f) {
                #pragma unroll
                for (int j = 0; j < 32; j++) orow[j] *= alpha;
            }
        }
        __syncthreads();

        // O += P @ V   (64x128, K-dim 64)
        {
            wmma::fragment<wmma::accumulator, 16, 16, 8, float> oacc[4];
            #pragma unroll
            for (int j = 0; j < 4; j++)
                wmma::load_matrix_sync(oacc[j], Os + (wr * 16) * LQT + wc * 64 + j * 16,
                                       LQT, wmma::mem_row_major);
            #pragma unroll
            for (int kk = 0; kk < BC; kk += 8) {
                wmma::fragment<wmma::matrix_a, 16, 16, 8, wmma::precision::tf32, wmma::row_major> a;
                wmma::load_matrix_sync(a, Ss + (wr * 16) * LST + kk, LST);
                #pragma unroll
                for (int e = 0; e < a.num_elements; e++) a.x[e] = wmma::__float_to_tf32(a.x[e]);
                #pragma unroll
                for (int j = 0; j < 4; j++) {
                    wmma::fragment<wmma::matrix_b, 16, 16, 8, wmma::precision::tf32, wmma::row_major> bfr;
                    wmma::load_matrix_sync(bfr, Vs + kk * LQT + wc * 64 + j * 16, LQT);
                    #pragma unroll
                    for (int e = 0; e < bfr.num_elements; e++) bfr.x[e] = wmma::__float_to_tf32(bfr.x[e]);
                    wmma::mma_sync(oacc[j], a, bfr, oacc[j]);
                }
            }
            #pragma unroll
            for (int j = 0; j < 4; j++)
                wmma::store_matrix_sync(Os + (wr * 16) * LQT + wc * 64 + j * 16,
                                        oacc[j], LQT, wmma::mem_row_major);
        }
        __syncthreads();
    }

    // epilogue: O / l  -> gmem
    {
        int i   = tid >> 2;
        int sub = tid & 3;
        float inv = 1.0f / lrow[i];
        float* orow = Os + i * LQT + sub * 32;
        float* og   = Og + i * HD  + sub * 32;
        #pragma unroll
        for (int j = 0; j < 32; j += 4) {
            float4 v = *(float4*)(orow + j);
            v.x *= inv; v.y *= inv; v.z *= inv; v.w *= inv;
            *(float4*)(og + j) = v;
        }
    }
}

// ------------- [B,H,T,D] -> [B,T,C] head merge -------------------------------
__global__ __launch_bounds__(256) void transpose_o()
{
    size_t idx = (size_t)blockIdx.x * 256 + threadIdx.x;   // float4 index
    int col4 = (int)(idx & 511);          // C/4 = 512
    size_t row = idx >> 9;                // b*SEQ + t
    int b = (int)(row >> 11);
    int t = (int)(row & 2047);
    int h  = col4 >> 5;
    int d4 = col4 & 31;
    float4 v = ((const float4*)g_o)[((size_t)(b * NH + h) * SEQ + t) * 32 + d4];
    ((float4*)g_attn)[idx] = v;
}

// ------------- bias add on final output --------------------------------------
__global__ __launch_bounds__(256) void bias_add(float* __restrict__ out,
                                                const float* __restrict__ bias)
{
    size_t idx = (size_t)blockIdx.x * 256 + threadIdx.x;   // float4 index
    int col4 = (int)(idx & 511);
    float4 v  = ((float4*)out)[idx];
    float4 bb = ((const float4*)bias)[col4];
    v.x += bb.x; v.y += bb.y; v.z += bb.z; v.w += bb.w;
    ((float4*)out)[idx] = v;
}

// -----------------------------------------------------------------------------
extern "C" void kernel_launch(void* const* d_in, const int* in_sizes, int n_in,
                              void* d_out, int out_size)
{
    const float* x     = (const float*)d_in[0];
    const float* w_qkv = (const float*)d_in[1];
    const float* b_qkv = (const float*)d_in[2];
    const float* w_out = (const float*)d_in[3];
    const float* b_out = (const float*)d_in[4];
    float* out = (float*)d_out;

    float *qkv_ptr, *attn_ptr;
    cudaGetSymbolAddress((void**)&qkv_ptr, g_qkv);
    cudaGetSymbolAddress((void**)&attn_ptr, g_attn);

    size_t flash_smem = (size_t)FLASH_SMEM_FLOATS * sizeof(float);
    cudaFuncSetAttribute(flash_attn, cudaFuncAttributeMaxDynamicSharedMemorySize,
                         (int)flash_smem);

    // 1) qkv = x @ w_qkv^T       [8192,2048] x [6144,2048]^T
    gemm_tf32<<<dim3(QKV_N / BN, (BATCH * SEQ) / BM), 256>>>(
        x, w_qkv, qkv_ptr, BATCH * SEQ, QKV_N, CH);

    // 2) bias + RoPE + split heads
    rope_split<<<BATCH * SEQ, 256>>>(b_qkv);

    // 3) causal flash attention
    flash_attn<<<dim3(SEQ / BR, NH, BATCH), 256, flash_smem>>>();

    // 4) merge heads
    transpose_o<<<(BATCH * SEQ * CH / 4) / 256, 256>>>();

    // 5) out = attn @ w_out^T
    gemm_tf32<<<dim3(CH / BN, (BATCH * SEQ) / BM), 256>>>(
        attn_ptr, w_out, out, BATCH * SEQ, CH, CH);

    // 6) + b_out
    bias_add<<<(BATCH * SEQ * CH / 4) / 256, 256>>>(out, b_out);
}

// round 4
// speedup vs baseline: 1.0896x; 1.0896x over previous
#include <cuda_runtime.h>
#include <mma.h>
#include <math.h>
#include <stdint.h>

using namespace nvcuda;

#define BATCH 4
#define SEQ   2048
#define CH    2048
#define NH    16
#define HD    128
#define QKV_N 6144

// ---------------- scratch (no allocs allowed -> __device__ globals) ----------
__device__ float g_qkv[(size_t)BATCH * SEQ * QKV_N];       // 201 MB
__device__ float g_q[(size_t)BATCH * NH * SEQ * HD];       // 67 MB
__device__ float g_k[(size_t)BATCH * NH * SEQ * HD];
__device__ float g_v[(size_t)BATCH * NH * SEQ * HD];
__device__ float g_o[(size_t)BATCH * NH * SEQ * HD];
__device__ float g_attn[(size_t)BATCH * SEQ * CH];         // 67 MB

// ---------------- cp.async helpers ------------------------------------------
__device__ __forceinline__ void cp_async16(void* smem_dst, const void* gmem_src) {
    unsigned s = (unsigned)__cvta_generic_to_shared(smem_dst);
    asm volatile("cp.async.cg.shared.global [%0], [%1], 16;\n" :: "r"(s), "l"(gmem_src));
}
__device__ __forceinline__ void cp_commit() {
    asm volatile("cp.async.commit_group;\n");
}
template <int N>
__device__ __forceinline__ void cp_wait() {
    asm volatile("cp.async.wait_group %0;\n" :: "n"(N));
}

// -------- pipelined TF32 GEMM: C[M,N] = A[M,K] @ B[N,K]^T --------------------
// 128x128 tile, BK=32, 3-stage cp.async pipeline, 8 warps each 32x64.
#define BM 128
#define BN 128
#define BK 32
#define LDA 36
#define LDB 36
#define STAGE_FLOATS (BM * LDA + BN * LDB)   // 9216 floats = 36864 B
#define GEMM_STAGES 3
#define GEMM_SMEM_BYTES (STAGE_FLOATS * GEMM_STAGES * 4)

__global__ __launch_bounds__(256, 2) void gemm_tf32(
    const float* __restrict__ A, const float* __restrict__ Bm,
    float* __restrict__ C, int M, int N, int K)
{
    extern __shared__ float smem[];

    int tid = threadIdx.x;
    int wid = tid >> 5;
    int wr  = wid & 3;     // warp row: 32 rows each
    int wc  = wid >> 2;    // warp col: 64 cols each
    int bm  = blockIdx.y * BM;
    int bn  = blockIdx.x * BN;

    // per-thread load coords: 1024 float4 per tile side, 4 per thread
    int lrow = tid >> 3;        // 0..31 base rows (stride 32 over 4 iters)
    int lc4  = tid & 7;         // float4 column 0..7

    const float* Abase = A + (size_t)(bm) * K;
    const float* Bbase = Bm + (size_t)(bn) * K;

    wmma::fragment<wmma::accumulator, 16, 16, 8, float> acc[2][4];
    #pragma unroll
    for (int i = 0; i < 2; i++)
        #pragma unroll
        for (int j = 0; j < 4; j++) wmma::fill_fragment(acc[i][j], 0.0f);

    int nk = K / BK;

    // prefetch stages 0,1
    #pragma unroll
    for (int s = 0; s < GEMM_STAGES - 1; s++) {
        float* As = smem + s * STAGE_FLOATS;
        float* Bs = As + BM * LDA;
        int k0 = s * BK;
        #pragma unroll
        for (int r = 0; r < 4; r++) {
            int row = lrow + r * 32;
            cp_async16(As + row * LDA + lc4 * 4, Abase + (size_t)row * K + k0 + lc4 * 4);
            cp_async16(Bs + row * LDB + lc4 * 4, Bbase + (size_t)row * K + k0 + lc4 * 4);
        }
        cp_commit();
    }

    for (int kt = 0; kt < nk; kt++) {
        cp_wait<1>();
        __syncthreads();

        float* As = smem + (kt % GEMM_STAGES) * STAGE_FLOATS;
        float* Bs = As + BM * LDA;

        #pragma unroll
        for (int kk = 0; kk < BK; kk += 8) {
            wmma::fragment<wmma::matrix_a, 16, 16, 8, wmma::precision::tf32, wmma::row_major> a[2];
            wmma::fragment<wmma::matrix_b, 16, 16, 8, wmma::precision::tf32, wmma::col_major> b[4];
            #pragma unroll
            for (int i = 0; i < 2; i++) {
                wmma::load_matrix_sync(a[i], As + (wr * 32 + i * 16) * LDA + kk, LDA);
                #pragma unroll
                for (int e = 0; e < a[i].num_elements; e++)
                    a[i].x[e] = wmma::__float_to_tf32(a[i].x[e]);
            }
            #pragma unroll
            for (int j = 0; j < 4; j++) {
                wmma::load_matrix_sync(b[j], Bs + (wc * 64 + j * 16) * LDB + kk, LDB);
                #pragma unroll
                for (int e = 0; e < b[j].num_elements; e++)
                    b[j].x[e] = wmma::__float_to_tf32(b[j].x[e]);
            }
            #pragma unroll
            for (int i = 0; i < 2; i++)
                #pragma unroll
                for (int j = 0; j < 4; j++)
                    wmma::mma_sync(acc[i][j], a[i], b[j], acc[i][j]);
        }

        // prefetch stage kt+2
        int pf = kt + GEMM_STAGES - 1;
        if (pf < nk) {
            float* Ap = smem + (pf % GEMM_STAGES) * STAGE_FLOATS;
            float* Bp = Ap + BM * LDA;
            int k0 = pf * BK;
            #pragma unroll
            for (int r = 0; r < 4; r++) {
                int row = lrow + r * 32;
                cp_async16(Ap + row * LDA + lc4 * 4, Abase + (size_t)row * K + k0 + lc4 * 4);
                cp_async16(Bp + row * LDB + lc4 * 4, Bbase + (size_t)row * K + k0 + lc4 * 4);
            }
        }
        cp_commit();   // always commit (possibly empty) to keep wait<1> semantics
    }

    #pragma unroll
    for (int i = 0; i < 2; i++)
        #pragma unroll
        for (int j = 0; j < 4; j++)
            wmma::store_matrix_sync(
                C + (size_t)(bm + wr * 32 + i * 16) * N + bn + wc * 64 + j * 16,
                acc[i][j], N, wmma::mem_row_major);
}

// ------------- bias + RoPE + split into [B,H,T,D] q/k/v ----------------------
__global__ __launch_bounds__(256) void rope_split(const float* __restrict__ bias)
{
    int token = blockIdx.x;              // b*SEQ + t
    int b = token >> 11;                 // /2048
    int t = token & 2047;
    const float2* row = (const float2*)(g_qkv + (size_t)token * QKV_N);
    const float2* bq  = (const float2*)bias;
    int tid = threadIdx.x;

    const float L2B_OVER_HALF = 13.287712379549449f / 64.0f;  // log2(10000)/64

    // q and k: 1024 rotation pairs each
    for (int p = tid; p < 1024; p += 256) {
        int h = p >> 6;
        int i = p & 63;
        float theta = exp2f(-(float)i * L2B_OVER_HALF);
        float ang = (float)t * theta;
        float s, c;
        sincosf(ang, &s, &c);

        size_t dst = ((size_t)(b * NH + h) * SEQ + t) * 64 + i;

        float2 xq = row[p];
        float2 bb = bq[p];
        float x1 = xq.x + bb.x, x2 = xq.y + bb.y;
        float2 oq;
        oq.x = x1 * c - x2 * s;
        oq.y = x1 * s + x2 * c;
        ((float2*)g_q)[dst] = oq;

        float2 xk = row[1024 + p];
        float2 bk = bq[1024 + p];
        float k1 = xk.x + bk.x, k2 = xk.y + bk.y;
        float2 ok;
        ok.x = k1 * c - k2 * s;
        ok.y = k1 * s + k2 * c;
        ((float2*)g_k)[dst] = ok;
    }
    // v: copy + bias
    for (int p = tid; p < 1024; p += 256) {
        int h = p >> 6;
        int i = p & 63;
        float2 xv = row[2048 + p];
        float2 bv = bq[2048 + p];
        float2 ov;
        ov.x = xv.x + bv.x;
        ov.y = xv.y + bv.y;
        ((float2*)g_v)[((size_t)(b * NH + h) * SEQ + t) * 64 + i] = ov;
    }
}

// ------------------------- flash attention -----------------------------------
#define BR 64
#define BC 64
#define LQT 132   // ld for Q/K/V/O tiles
#define LST 68    // ld for S tile
// smem floats: Q 8448, K 8448, V 8448, O 8448, S 4352, m 64, l 64
#define FLASH_SMEM_FLOATS (8448*4 + 4352 + 128)

__global__ __launch_bounds__(256) void flash_attn()
{
    extern __shared__ float sm[];
    float* Qs = sm;
    float* Ks = sm + 8448;
    float* Vs = sm + 16896;
    float* Os = sm + 25344;
    float* Ss = sm + 33792;
    float* mrow = sm + 38144;
    float* lrow = sm + 38208;

    int qt = blockIdx.x, h = blockIdx.y, b = blockIdx.z;
    int tid = threadIdx.x;
    int wid = tid >> 5;
    int wr = wid & 3;
    int wc = wid >> 2;

    const float* Qg = g_q + ((size_t)(b * NH + h) * SEQ + qt * BR) * HD;
    const float* Kg = g_k + (size_t)(b * NH + h) * SEQ * HD;
    const float* Vg = g_v + (size_t)(b * NH + h) * SEQ * HD;
    float*       Og = g_o + ((size_t)(b * NH + h) * SEQ + qt * BR) * HD;

    // load Q tile, init O/m/l
    #pragma unroll
    for (int r = 0; r < 8; r++) {
        int idx = tid + r * 256;
        int row = idx >> 5;
        int c4  = idx & 31;
        *(float4*)(Qs + row * LQT + c4 * 4) = *(const float4*)(Qg + row * HD + c4 * 4);
        *(float4*)(Os + row * LQT + c4 * 4) = make_float4(0.f, 0.f, 0.f, 0.f);
    }
    if (tid < 64) { mrow[tid] = -1e30f; lrow[tid] = 0.0f; }
    __syncthreads();

    const float scale = 0.08838834764831845f;  // 1/sqrt(128)

    for (int kt = 0; kt <= qt; kt++) {
        // load K and V tiles
        #pragma unroll
        for (int r = 0; r < 8; r++) {
            int idx = tid + r * 256;
            int row = idx >> 5;
            int c4  = idx & 31;
            *(float4*)(Ks + row * LQT + c4 * 4) =
                *(const float4*)(Kg + (size_t)(kt * BC + row) * HD + c4 * 4);
            *(float4*)(Vs + row * LQT + c4 * 4) =
                *(const float4*)(Vg + (size_t)(kt * BC + row) * HD + c4 * 4);
        }
        __syncthreads();

        // S = Q @ K^T  (64x64, K-dim 128)
        {
            wmma::fragment<wmma::accumulator, 16, 16, 8, float> sacc[2];
            wmma::fill_fragment(sacc[0], 0.0f);
            wmma::fill_fragment(sacc[1], 0.0f);
            #pragma unroll
            for (int kk = 0; kk < HD; kk += 8) {
                wmma::fragment<wmma::matrix_a, 16, 16, 8, wmma::precision::tf32, wmma::row_major> a;
                wmma::load_matrix_sync(a, Qs + (wr * 16) * LQT + kk, LQT);
                #pragma unroll
                for (int e = 0; e < a.num_elements; e++) a.x[e] = wmma::__float_to_tf32(a.x[e]);
                #pragma unroll
                for (int j = 0; j < 2; j++) {
                    wmma::fragment<wmma::matrix_b, 16, 16, 8, wmma::precision::tf32, wmma::col_major> bfr;
                    wmma::load_matrix_sync(bfr, Ks + (wc * 32 + j * 16) * LQT + kk, LQT);
                    #pragma unroll
                    for (int e = 0; e < bfr.num_elements; e++) bfr.x[e] = wmma::__float_to_tf32(bfr.x[e]);
                    wmma::mma_sync(sacc[j], a, bfr, sacc[j]);
                }
            }
            #pragma unroll
            for (int j = 0; j < 2; j++)
                wmma::store_matrix_sync(Ss + (wr * 16) * LST + wc * 32 + j * 16,
                                        sacc[j], LST, wmma::mem_row_major);
        }
        __syncthreads();

        // online softmax (4 threads per row)
        {
            int i   = tid >> 2;
            int sub = tid & 3;
            int gq  = qt * BR + i;
            float* srow = Ss + i * LST;

            float vals[16];
            float mx = -1e30f;
            #pragma unroll
            for (int jj = 0; jj < 16; jj++) {
                int j  = sub + jj * 4;
                int gk = kt * BC + j;
                float sv = (gk <= gq) ? srow[j] * scale : -1e30f;
                vals[jj] = sv;
                mx = fmaxf(mx, sv);
            }
            mx = fmaxf(mx, __shfl_xor_sync(0xffffffffu, mx, 1));
            mx = fmaxf(mx, __shfl_xor_sync(0xffffffffu, mx, 2));

            float mold = mrow[i];            // all 4 lanes read
            float mnew = fmaxf(mold, mx);
            float sum = 0.0f;
            #pragma unroll
            for (int jj = 0; jj < 16; jj++) {
                float p = __expf(vals[jj] - mnew);
                sum += p;
                srow[sub + jj * 4] = p;
            }
            sum += __shfl_xor_sync(0xffffffffu, sum, 1);
            sum += __shfl_xor_sync(0xffffffffu, sum, 2);

            __syncwarp();                    // order reads of mrow before the write
            float alpha = __expf(mold - mnew);
            if (sub == 0) {
                mrow[i] = mnew;
                lrow[i] = lrow[i] * alpha + sum;
            }
            // rescale O row
            float* orow = Os + i * LQT + sub * 32;
            if (alpha != 1.0f) {
                #pragma unroll
                for (int j = 0; j < 32; j++) orow[j] *= alpha;
            }
        }
        __syncthreads();

        // O += P @ V   (64x128, K-dim 64)
        {
            wmma::fragment<wmma::accumulator, 16, 16, 8, float> oacc[4];
            #pragma unroll
            for (int j = 0; j < 4; j++)
                wmma::load_matrix_sync(oacc[j], Os + (wr * 16) * LQT + wc * 64 + j * 16,
                                       LQT, wmma::mem_row_major);
            #pragma unroll
            for (int kk = 0; kk < BC; kk += 8) {
                wmma::fragment<wmma::matrix_a, 16, 16, 8, wmma::precision::tf32, wmma::row_major> a;
                wmma::load_matrix_sync(a, Ss + (wr * 16) * LST + kk, LST);
                #pragma unroll
                for (int e = 0; e < a.num_elements; e++) a.x[e] = wmma::__float_to_tf32(a.x[e]);
                #pragma unroll
                for (int j = 0; j < 4; j++) {
                    wmma::fragment<wmma::matrix_b, 16, 16, 8, wmma::precision::tf32, wmma::row_major> bfr;
                    wmma::load_matrix_sync(bfr, Vs + kk * LQT + wc * 64 + j * 16, LQT);
                    #pragma unroll
                    for (int e = 0; e < bfr.num_elements; e++) bfr.x[e] = wmma::__float_to_tf32(bfr.x[e]);
                    wmma::mma_sync(oacc[j], a, bfr, oacc[j]);
                }
            }
            #pragma unroll
            for (int j = 0; j < 4; j++)
                wmma::store_matrix_sync(Os + (wr * 16) * LQT + wc * 64 + j * 16,
                                        oacc[j], LQT, wmma::mem_row_major);
        }
        __syncthreads();
    }

    // epilogue: O / l  -> gmem
    {
        int i   = tid >> 2;
        int sub = tid & 3;
        float inv = 1.0f / lrow[i];
        float* orow = Os + i * LQT + sub * 32;
        float* og   = Og + i * HD  + sub * 32;
        #pragma unroll
        for (int j = 0; j < 32; j += 4) {
            float4 v = *(float4*)(orow + j);
            v.x *= inv; v.y *= inv; v.z *= inv; v.w *= inv;
            *(float4*)(og + j) = v;
        }
    }
}

// ------------- [B,H,T,D] -> [B,T,C] head merge -------------------------------
__global__ __launch_bounds__(256) void transpose_o()
{
    size_t idx = (size_t)blockIdx.x * 256 + threadIdx.x;   // float4 index
    int col4 = (int)(idx & 511);          // C/4 = 512
    size_t row = idx >> 9;                // b*SEQ + t
    int b = (int)(row >> 11);
    int t = (int)(row & 2047);
    int h  = col4 >> 5;
    int d4 = col4 & 31;
    float4 v = ((const float4*)g_o)[((size_t)(b * NH + h) * SEQ + t) * 32 + d4];
    ((float4*)g_attn)[idx] = v;
}

// ------------- bias add on final output --------------------------------------
__global__ __launch_bounds__(256) void bias_add(float* __restrict__ out,
                                                const float* __restrict__ bias)
{
    size_t idx = (size_t)blockIdx.x * 256 + threadIdx.x;   // float4 index
    int col4 = (int)(idx & 511);
    float4 v  = ((float4*)out)[idx];
    float4 bb = ((const float4*)bias)[col4];
    v.x += bb.x; v.y += bb.y; v.z += bb.z; v.w += bb.w;
    ((float4*)out)[idx] = v;
}

// -----------------------------------------------------------------------------
extern "C" void kernel_launch(void* const* d_in, const int* in_sizes, int n_in,
                              void* d_out, int out_size)
{
    const float* x     = (const float*)d_in[0];
    const float* w_qkv = (const float*)d_in[1];
    const float* b_qkv = (const float*)d_in[2];
    const float* w_out = (const float*)d_in[3];
    const float* b_out = (const float*)d_in[4];
    float* out = (float*)d_out;

    float *qkv_ptr, *attn_ptr;
    cudaGetSymbolAddress((void**)&qkv_ptr, g_qkv);
    cudaGetSymbolAddress((void**)&attn_ptr, g_attn);

    size_t flash_smem = (size_t)FLASH_SMEM_FLOATS * sizeof(float);
    cudaFuncSetAttribute(flash_attn, cudaFuncAttributeMaxDynamicSharedMemorySize,
                         (int)flash_smem);
    cudaFuncSetAttribute(gemm_tf32, cudaFuncAttributeMaxDynamicSharedMemorySize,
                         GEMM_SMEM_BYTES);

    // 1) qkv = x @ w_qkv^T       [8192,2048] x [6144,2048]^T
    gemm_tf32<<<dim3(QKV_N / BN, (BATCH * SEQ) / BM), 256, GEMM_SMEM_BYTES>>>(
        x, w_qkv, qkv_ptr, BATCH * SEQ, QKV_N, CH);

    // 2) bias + RoPE + split heads
    rope_split<<<BATCH * SEQ, 256>>>(b_qkv);

    // 3) causal flash attention
    flash_attn<<<dim3(SEQ / BR, NH, BATCH), 256, flash_smem>>>();

    // 4) merge heads
    transpose_o<<<(BATCH * SEQ * CH / 4) / 256, 256>>>();

    // 5) out = attn @ w_out^T
    gemm_tf32<<<dim3(CH / BN, (BATCH * SEQ) / BM), 256, GEMM_SMEM_BYTES>>>(
        attn_ptr, w_out, out, BATCH * SEQ, CH, CH);

    // 6) + b_out
    bias_add<<<(BATCH * SEQ * CH / 4) / 256, 256>>>(out, b_out);
}

// round 5
// speedup vs baseline: 1.4371x; 1.3189x over previous
#include <cuda_runtime.h>
#include <mma.h>
#include <math.h>
#include <stdint.h>

using namespace nvcuda;

#define BATCH 4
#define SEQ   2048
#define CH    2048
#define NH    16
#define HD    128
#define QKV_N 6144

// ---------------- scratch (no allocs allowed -> __device__ globals) ----------
__device__ float  g_q[(size_t)BATCH * NH * SEQ * HD];
__device__ float  g_k[(size_t)BATCH * NH * SEQ * HD];
__device__ float  g_v[(size_t)BATCH * NH * SEQ * HD];
__device__ float  g_o[(size_t)BATCH * NH * SEQ * HD];
__device__ float2 g_rope[SEQ * 64];          // (sin, cos) per (t, pair)

// ---------------- helpers ----------------------------------------------------
__device__ __forceinline__ void cp_async16(void* smem_dst, const void* gmem_src) {
    unsigned s = (unsigned)__cvta_generic_to_shared(smem_dst);
    asm volatile("cp.async.cg.shared.global [%0], [%1], 16;\n" :: "r"(s), "l"(gmem_src));
}
__device__ __forceinline__ void cp_commit() {
    asm volatile("cp.async.commit_group;\n");
}
template <int N>
__device__ __forceinline__ void cp_wait() {
    asm volatile("cp.async.wait_group %0;\n" :: "n"(N));
}
__device__ __forceinline__ unsigned f2tf(float x) {   // round-to-nearest tf32
    unsigned r; asm("cvt.rna.tf32.f32 %0, %1;" : "=r"(r) : "f"(x)); return r;
}
__device__ __forceinline__ void mma_tf32(float* d,
    unsigned a0, unsigned a1, unsigned a2, unsigned a3,
    unsigned b0, unsigned b1)
{
    asm volatile(
        "mma.sync.aligned.m16n8k8.row.col.f32.tf32.tf32.f32 "
        "{%0,%1,%2,%3}, {%4,%5,%6,%7}, {%8,%9}, {%0,%1,%2,%3};\n"
        : "+f"(d[0]), "+f"(d[1]), "+f"(d[2]), "+f"(d[3])
        : "r"(a0), "r"(a1), "r"(a2), "r"(a3), "r"(b0), "r"(b1));
}

// ---------------- rope table --------------------------------------------------
__global__ void rope_table() {
    int idx = blockIdx.x * blockDim.x + threadIdx.x;   // 131072
    int t = idx >> 6, i = idx & 63;
    float theta = exp2f(-(float)i * (13.287712379549449f / 64.0f));
    float s, c; sincosf((float)t * theta, &s, &c);
    g_rope[idx] = make_float2(s, c);
}

// -------- pipelined TF32 GEMM core macro pieces -------------------------------
#define BM 128
#define BN 128
#define BK 32
#define LDA 36
#define LDB 36
#define STAGE_FLOATS (BM * LDA + BN * LDB)   // 9216 floats
#define GEMM_STAGES 3
#define GEMM_SMEM_BYTES (STAGE_FLOATS * GEMM_STAGES * 4)
#define CS_LD 132

// ---- QKV GEMM: qkv = x @ w_qkv^T, fused bias + RoPE + tf32-round + scatter ---
__global__ __launch_bounds__(256, 2) void gemm_qkv(
    const float* __restrict__ A, const float* __restrict__ Bm,
    const float* __restrict__ bias)
{
    extern __shared__ float smem[];
    const int K = CH;
    int tid = threadIdx.x;
    int wid = tid >> 5;
    int wr  = wid & 3;
    int wc  = wid >> 2;
    int bm  = blockIdx.y * BM;
    int n0  = blockIdx.x * BN;

    int lrow = tid >> 3;
    int lc4  = tid & 7;
    const float* Abase = A + (size_t)bm * K;
    const float* Bbase = Bm + (size_t)n0 * K;

    wmma::fragment<wmma::accumulator, 16, 16, 8, float> acc[2][4];
    #pragma unroll
    for (int i = 0; i < 2; i++)
        #pragma unroll
        for (int j = 0; j < 4; j++) wmma::fill_fragment(acc[i][j], 0.0f);

    int nk = K / BK;
    #pragma unroll
    for (int s = 0; s < GEMM_STAGES - 1; s++) {
        float* As = smem + s * STAGE_FLOATS;
        float* Bs = As + BM * LDA;
        int k0 = s * BK;
        #pragma unroll
        for (int r = 0; r < 4; r++) {
            int row = lrow + r * 32;
            cp_async16(As + row * LDA + lc4 * 4, Abase + (size_t)row * K + k0 + lc4 * 4);
            cp_async16(Bs + row * LDB + lc4 * 4, Bbase + (size_t)row * K + k0 + lc4 * 4);
        }
        cp_commit();
    }

    for (int kt = 0; kt < nk; kt++) {
        cp_wait<1>();
        __syncthreads();
        float* As = smem + (kt % GEMM_STAGES) * STAGE_FLOATS;
        float* Bs = As + BM * LDA;
        #pragma unroll
        for (int kk = 0; kk < BK; kk += 8) {
            wmma::fragment<wmma::matrix_a, 16, 16, 8, wmma::precision::tf32, wmma::row_major> a[2];
            wmma::fragment<wmma::matrix_b, 16, 16, 8, wmma::precision::tf32, wmma::col_major> b[4];
            #pragma unroll
            for (int i = 0; i < 2; i++) {
                wmma::load_matrix_sync(a[i], As + (wr * 32 + i * 16) * LDA + kk, LDA);
                #pragma unroll
                for (int e = 0; e < a[i].num_elements; e++)
                    a[i].x[e] = wmma::__float_to_tf32(a[i].x[e]);
            }
            #pragma unroll
            for (int j = 0; j < 4; j++) {
                wmma::load_matrix_sync(b[j], Bs + (wc * 64 + j * 16) * LDB + kk, LDB);
                #pragma unroll
                for (int e = 0; e < b[j].num_elements; e++)
                    b[j].x[e] = wmma::__float_to_tf32(b[j].x[e]);
            }
            #pragma unroll
            for (int i = 0; i < 2; i++)
                #pragma unroll
                for (int j = 0; j < 4; j++)
                    wmma::mma_sync(acc[i][j], a[i], b[j], acc[i][j]);
        }
        int pf = kt + GEMM_STAGES - 1;
        if (pf < nk) {
            float* Ap = smem + (pf % GEMM_STAGES) * STAGE_FLOATS;
            float* Bp = Ap + BM * LDA;
            int k0 = pf * BK;
            #pragma unroll
            for (int r = 0; r < 4; r++) {
                int row = lrow + r * 32;
                cp_async16(Ap + row * LDA + lc4 * 4, Abase + (size_t)row * K + k0 + lc4 * 4);
                cp_async16(Bp + row * LDB + lc4 * 4, Bbase + (size_t)row * K + k0 + lc4 * 4);
            }
        }
        cp_commit();
    }

    // ---- epilogue: stage tile to smem, then bias + rope + scatter -----------
    cp_wait<0>();
    __syncthreads();                 // all warps done with stage buffers
    float* Cs = smem;                // 128 x CS_LD
    #pragma unroll
    for (int i = 0; i < 2; i++)
        #pragma unroll
        for (int j = 0; j < 4; j++)
            wmma::store_matrix_sync(Cs + (wr * 32 + i * 16) * CS_LD + wc * 64 + j * 16,
                                    acc[i][j], CS_LD, wmma::mem_row_major);
    __syncthreads();

    int sel = n0 >> 11;               // 0=q 1=k 2=v
    int h   = (n0 >> 7) & 15;
    float* dst = (sel == 0) ? g_q : (sel == 1) ? g_k : g_v;

    int r   = tid >> 1;               // 0..127
    int sub = tid & 1;                // half of the 64 pairs
    int token = bm + r;
    int b = token >> 11;
    int t = token & 2047;
    float* drow = dst + ((size_t)(b * NH + h) * SEQ + t) * HD;
    const float* crow = Cs + r * CS_LD;
    const float2* scrow = g_rope + t * 64;

    if (sel < 2) {
        #pragma unroll
        for (int p = sub * 32; p < sub * 32 + 32; p++) {
            float2 xv = *(const float2*)&crow[2 * p];
            float2 bb = *(const float2*)&bias[n0 + 2 * p];
            float x1 = xv.x + bb.x, x2 = xv.y + bb.y;
            float2 sc = scrow[p];
            float r1 = x1 * sc.y - x2 * sc.x;
            float r2 = x1 * sc.x + x2 * sc.y;
            float2 o;
            o.x = __uint_as_float(f2tf(r1));
            o.y = __uint_as_float(f2tf(r2));
            *(float2*)&drow[2 * p] = o;
        }
    } else {
        #pragma unroll
        for (int p = sub * 32; p < sub * 32 + 32; p++) {
            float2 xv = *(const float2*)&crow[2 * p];
            float2 bb = *(const float2*)&bias[n0 + 2 * p];
            float2 o;
            o.x = __uint_as_float(f2tf(xv.x + bb.x));
            o.y = __uint_as_float(f2tf(xv.y + bb.y));
            *(float2*)&drow[2 * p] = o;
        }
    }
}

// ---- proj GEMM: out = attn @ w_out^T, A read directly from g_o layout --------
__global__ __launch_bounds__(256, 2) void gemm_proj(
    const float* __restrict__ Bm, float* __restrict__ C)
{
    extern __shared__ float smem[];
    const int K = CH, N = CH;
    int tid = threadIdx.x;
    int wid = tid >> 5;
    int wr  = wid & 3;
    int wc  = wid >> 2;
    int bm  = blockIdx.y * BM;
    int bn  = blockIdx.x * BN;

    int lrow = tid >> 3;
    int lc4  = tid & 7;

    // A row base pointers into g_o [B,H,T,D]
    const float* arow[4];
    #pragma unroll
    for (int r = 0; r < 4; r++) {
        int token = bm + lrow + r * 32;
        int b = token >> 11, t = token & 2047;
        arow[r] = g_o + ((size_t)b * NH * SEQ + t) * HD;
    }
    const float* Bbase = Bm + (size_t)bn * K;

    wmma::fragment<wmma::accumulator, 16, 16, 8, float> acc[2][4];
    #pragma unroll
    for (int i = 0; i < 2; i++)
        #pragma unroll
        for (int j = 0; j < 4; j++) wmma::fill_fragment(acc[i][j], 0.0f);

    int nk = K / BK;
    #pragma unroll
    for (int s = 0; s < GEMM_STAGES - 1; s++) {
        float* As = smem + s * STAGE_FLOATS;
        float* Bs = As + BM * LDA;
        int k0 = s * BK;
        size_t aoff = (size_t)(k0 >> 7) * (SEQ * HD) + (k0 & 127) + lc4 * 4;
        #pragma unroll
        for (int r = 0; r < 4; r++) {
            int row = lrow + r * 32;
            cp_async16(As + row * LDA + lc4 * 4, arow[r] + aoff);
            cp_async16(Bs + row * LDB + lc4 * 4, Bbase + (size_t)row * K + k0 + lc4 * 4);
        }
        cp_commit();
    }

    for (int kt = 0; kt < nk; kt++) {
        cp_wait<1>();
        __syncthreads();
        float* As = smem + (kt % GEMM_STAGES) * STAGE_FLOATS;
        float* Bs = As + BM * LDA;
        #pragma unroll
        for (int kk = 0; kk < BK; kk += 8) {
            wmma::fragment<wmma::matrix_a, 16, 16, 8, wmma::precision::tf32, wmma::row_major> a[2];
            wmma::fragment<wmma::matrix_b, 16, 16, 8, wmma::precision::tf32, wmma::col_major> b[4];
            #pragma unroll
            for (int i = 0; i < 2; i++) {
                wmma::load_matrix_sync(a[i], As + (wr * 32 + i * 16) * LDA + kk, LDA);
                #pragma unroll
                for (int e = 0; e < a[i].num_elements; e++)
                    a[i].x[e] = wmma::__float_to_tf32(a[i].x[e]);
            }
            #pragma unroll
            for (int j = 0; j < 4; j++) {
                wmma::load_matrix_sync(b[j], Bs + (wc * 64 + j * 16) * LDB + kk, LDB);
                #pragma unroll
                for (int e = 0; e < b[j].num_elements; e++)
                    b[j].x[e] = wmma::__float_to_tf32(b[j].x[e]);
            }
            #pragma unroll
            for (int i = 0; i < 2; i++)
                #pragma unroll
                for (int j = 0; j < 4; j++)
                    wmma::mma_sync(acc[i][j], a[i], b[j], acc[i][j]);
        }
        int pf = kt + GEMM_STAGES - 1;
        if (pf < nk) {
            float* Ap = smem + (pf % GEMM_STAGES) * STAGE_FLOATS;
            float* Bp = Ap + BM * LDA;
            int k0 = pf * BK;
            size_t aoff = (size_t)(k0 >> 7) * (SEQ * HD) + (k0 & 127) + lc4 * 4;
            #pragma unroll
            for (int r = 0; r < 4; r++) {
                int row = lrow + r * 32;
                cp_async16(Ap + row * LDA + lc4 * 4, arow[r] + aoff);
                cp_async16(Bp + row * LDB + lc4 * 4, Bbase + (size_t)row * K + k0 + lc4 * 4);
            }
        }
        cp_commit();
    }

    #pragma unroll
    for (int i = 0; i < 2; i++)
        #pragma unroll
        for (int j = 0; j < 4; j++)
            wmma::store_matrix_sync(
                C + (size_t)(bm + wr * 32 + i * 16) * N + bn + wc * 64 + j * 16,
                acc[i][j], N, wmma::mem_row_major);
}

// ------------------------- flash attention (raw mma) --------------------------
// BR=128 q-rows per CTA (8 warps x 16 rows), BC=64 keys per iter.
// O, softmax stats fully register-resident. cp.async double-buffered K/V.
#define FBR 128
#define FBC 64
#define LQ  132
#define LK  132
#define FLASH_SMEM_BYTES ((FBR*LQ + 2*FBC*LK + 2*FBC*LK) * 4)   // 202752

__global__ __launch_bounds__(256, 1) void flash_attn()
{
    extern __shared__ float sm[];
    float* Qs  = sm;                     // 128 x 132
    float* Ksb = sm + FBR * LQ;          // 2 x (64 x 132)
    float* Vsb = Ksb + 2 * FBC * LK;     // 2 x (64 x 132)

    int qt = blockIdx.x, h = blockIdx.y, b = blockIdx.z;
    int tid  = threadIdx.x;
    int wid  = tid >> 5;
    int lane = tid & 31;
    int quad = lane >> 2;        // 0..7
    int qi   = lane & 3;         // 0..3

    const float* Qg = g_q + ((size_t)(b * NH + h) * SEQ + qt * FBR) * HD;
    const float* Kg = g_k + (size_t)(b * NH + h) * SEQ * HD;
    const float* Vg = g_v + (size_t)(b * NH + h) * SEQ * HD;
    float*       Og = g_o + ((size_t)(b * NH + h) * SEQ + qt * FBR) * HD;

    int kmax = 2 * qt + 1;

    // initial loads: Q (16 f4/thread) + K0/V0 (8 f4/thread each)
    #pragma unroll
    for (int it = 0; it < 16; it++) {
        int idx = tid + it * 256;
        int r = idx >> 5, c4 = idx & 31;
        cp_async16(Qs + r * LQ + c4 * 4, Qg + (size_t)r * HD + c4 * 4);
    }
    #pragma unroll
    for (int it = 0; it < 8; it++) {
        int idx = tid + it * 256;
        int r = idx >> 5, c4 = idx & 31;
        cp_async16(Ksb + r * LK + c4 * 4, Kg + (size_t)r * HD + c4 * 4);
        cp_async16(Vsb + r * LK + c4 * 4, Vg + (size_t)r * HD + c4 * 4);
    }
    cp_commit();

    float o[16][4];
    #pragma unroll
    for (int n = 0; n < 16; n++)
        #pragma unroll
        for (int e = 0; e < 4; e++) o[n][e] = 0.0f;
    float m0 = -1e30f, m1 = -1e30f, l0 = 0.0f, l1 = 0.0f;

    const float scale = 0.08838834764831845f;
    int rowbase = wid * 16;
    int gq0 = qt * FBR + rowbase + quad;       // row of c0/c1
    // gq1 = gq0 + 8

    for (int kt = 0; kt <= kmax; kt++) {
        cp_wait<0>();
        __syncthreads();

        if (kt < kmax) {            // prefetch kt+1
            float* Kp = Ksb + ((kt + 1) & 1) * FBC * LK;
            float* Vp = Vsb + ((kt + 1) & 1) * FBC * LK;
            const float* Kgs = Kg + (size_t)(kt + 1) * FBC * HD;
            const float* Vgs = Vg + (size_t)(kt + 1) * FBC * HD;
            #pragma unroll
            for (int it = 0; it < 8; it++) {
                int idx = tid + it * 256;
                int r = idx >> 5, c4 = idx & 31;
                cp_async16(Kp + r * LK + c4 * 4, Kgs + (size_t)r * HD + c4 * 4);
                cp_async16(Vp + r * LK + c4 * 4, Vgs + (size_t)r * HD + c4 * 4);
            }
        }
        cp_commit();

        // warps whose rows are entirely above this key block: skip compute
        if (kt * FBC > qt * FBR + rowbase + 15) continue;

        const float* Kb = Ksb + (kt & 1) * FBC * LK;
        const float* Vb = Vsb + (kt & 1) * FBC * LK;

        // ---- S = Q @ K^T : per warp 16 x 64 (8 n8 blocks), k = 128 ----------
        float s[8][4];
        #pragma unroll
        for (int n = 0; n < 8; n++)
            #pragma unroll
            for (int e = 0; e < 4; e++) s[n][e] = 0.0f;

        #pragma unroll
        for (int ks = 0; ks < 16; ks++) {
            int kc = ks * 8;
            const float* qr0 = Qs + (rowbase + quad) * LQ + kc + qi;
            const float* qr1 = qr0 + 8 * LQ;
            unsigned a0 = *(const unsigned*)qr0;
            unsigned a1 = *(const unsigned*)qr1;
            unsigned a2 = *(const unsigned*)(qr0 + 4);
            unsigned a3 = *(const unsigned*)(qr1 + 4);
            #pragma unroll
            for (int n = 0; n < 8; n++) {
                const float* kb = Kb + (n * 8 + quad) * LK + kc + qi;
                unsigned b0 = *(const unsigned*)kb;
                unsigned b1 = *(const unsigned*)(kb + 4);
                mma_tf32(s[n], a0, a1, a2, a3, b0, b1);
            }
        }

        // ---- softmax (register + shfl only) ---------------------------------
        bool needmask = (kt >= 2 * qt);
        float mx0 = -1e30f, mx1 = -1e30f;
        #pragma unroll
        for (int n = 0; n < 8; n++) {
            #pragma unroll
            for (int e = 0; e < 4; e++) {
                float v = s[n][e] * scale;
                if (needmask) {
                    int col = kt * FBC + n * 8 + 2 * qi + (e & 1);
                    int row = gq0 + ((e >> 1) << 3);
                    if (col > row) v = -1e30f;
                }
                s[n][e] = v;
                if (e < 2) mx0 = fmaxf(mx0, v); else mx1 = fmaxf(mx1, v);
            }
        }
        mx0 = fmaxf(mx0, __shfl_xor_sync(0xffffffffu, mx0, 1));
        mx0 = fmaxf(mx0, __shfl_xor_sync(0xffffffffu, mx0, 2));
        mx1 = fmaxf(mx1, __shfl_xor_sync(0xffffffffu, mx1, 1));
        mx1 = fmaxf(mx1, __shfl_xor_sync(0xffffffffu, mx1, 2));

        float mn0 = fmaxf(m0, mx0), mn1 = fmaxf(m1, mx1);
        float al0 = __expf(m0 - mn0), al1 = __expf(m1 - mn1);
        float sum0 = 0.0f, sum1 = 0.0f;
        #pragma unroll
        for (int n = 0; n < 8; n++) {
            float p0 = __expf(s[n][0] - mn0);
            float p1 = __expf(s[n][1] - mn0);
            float p2 = __expf(s[n][2] - mn1);
            float p3 = __expf(s[n][3] - mn1);
            s[n][0] = p0; s[n][1] = p1; s[n][2] = p2; s[n][3] = p3;
            sum0 += p0 + p1; sum1 += p2 + p3;
        }
        sum0 += __shfl_xor_sync(0xffffffffu, sum0, 1);
        sum0 += __shfl_xor_sync(0xffffffffu, sum0, 2);
        sum1 += __shfl_xor_sync(0xffffffffu, sum1, 1);
        sum1 += __shfl_xor_sync(0xffffffffu, sum1, 2);
        l0 = l0 * al0 + sum0; m0 = mn0;
        l1 = l1 * al1 + sum1; m1 = mn1;

        #pragma unroll
        for (int n = 0; n < 16; n++) {
            o[n][0] *= al0; o[n][1] *= al0;
            o[n][2] *= al1; o[n][3] *= al1;
        }

        // ---- O += P @ V : k = 64 (8 k8 blocks), n = 128 (16 n8) -------------
        int base = lane & ~3;
        int src0 = base | (qi >> 1);
        int src2 = base | ((qi >> 1) + 2);
        bool hi = lane & 1;
        #pragma unroll
        for (int kb = 0; kb < 8; kb++) {
            float v00 = __shfl_sync(0xffffffffu, s[kb][0], src0);
            float v01 = __shfl_sync(0xffffffffu, s[kb][1], src0);
            float v20 = __shfl_sync(0xffffffffu, s[kb][0], src2);
            float v21 = __shfl_sync(0xffffffffu, s[kb][1], src2);
            float v10 = __shfl_sync(0xffffffffu, s[kb][2], src0);
            float v11 = __shfl_sync(0xffffffffu, s[kb][3], src0);
            float v30 = __shfl_sync(0xffffffffu, s[kb][2], src2);
            float v31 = __shfl_sync(0xffffffffu, s[kb][3], src2);
            unsigned a0 = f2tf(hi ? v01 : v00);
            unsigned a1 = f2tf(hi ? v11 : v10);
            unsigned a2 = f2tf(hi ? v21 : v20);
            unsigned a3 = f2tf(hi ? v31 : v30);
            #pragma unroll
            for (int n = 0; n < 16; n++) {
                const float* vb = Vb + (kb * 8 + qi) * LK + n * 8 + quad;
                unsigned b0 = *(const unsigned*)vb;
                unsigned b1 = *(const unsigned*)(vb + 4 * LK);
                mma_tf32(o[n], a0, a1, a2, a3, b0, b1);
            }
        }
    }

    // ---- epilogue: O/l -> smem (reuse K buffers) -> coalesced gmem ----------
    __syncthreads();
    float* Os = Ksb;                     // 128 x 132
    float inv0 = 1.0f / l0, inv1 = 1.0f / l1;
    int r0 = rowbase + quad, r1 = r0 + 8;
    #pragma unroll
    for (int n = 0; n < 16; n++) {
        int c = n * 8 + 2 * qi;
        *(float2*)&Os[r0 * LK + c] = make_float2(o[n][0] * inv0, o[n][1] * inv0);
        *(float2*)&Os[r1 * LK + c] = make_float2(o[n][2] * inv1, o[n][3] * inv1);
    }
    __syncthreads();
    #pragma unroll
    for (int it = 0; it < 16; it++) {
        int idx = tid + it * 256;
        int r = idx >> 5, c4 = idx & 31;
        *(float4*)(Og + (size_t)r * HD + c4 * 4) = *(float4*)&Os[r * LK + c4 * 4];
    }
}

// ------------- bias add on final output --------------------------------------
__global__ __launch_bounds__(256) void bias_add(float* __restrict__ out,
                                                const float* __restrict__ bias)
{
    size_t idx = (size_t)blockIdx.x * 256 + threadIdx.x;   // float4 index
    int col4 = (int)(idx & 511);
    float4 v  = ((float4*)out)[idx];
    float4 bb = ((const float4*)bias)[col4];
    v.x += bb.x; v.y += bb.y; v.z += bb.z; v.w += bb.w;
    ((float4*)out)[idx] = v;
}

// -----------------------------------------------------------------------------
extern "C" void kernel_launch(void* const* d_in, const int* in_sizes, int n_in,
                              void* d_out, int out_size)
{
    const float* x     = (const float*)d_in[0];
    const float* w_qkv = (const float*)d_in[1];
    const float* b_qkv = (const float*)d_in[2];
    const float* w_out = (const float*)d_in[3];
    const float* b_out = (const float*)d_in[4];
    float* out = (float*)d_out;

    cudaFuncSetAttribute(gemm_qkv, cudaFuncAttributeMaxDynamicSharedMemorySize,
                         GEMM_SMEM_BYTES);
    cudaFuncSetAttribute(gemm_proj, cudaFuncAttributeMaxDynamicSharedMemorySize,
                         GEMM_SMEM_BYTES);
    cudaFuncSetAttribute(flash_attn, cudaFuncAttributeMaxDynamicSharedMemorySize,
                         FLASH_SMEM_BYTES);

    // 0) rope tables (cheap, graph-replayed)
    rope_table<<<128, 1024>>>();

    // 1) qkv = x @ w_qkv^T fused bias+rope+split -> g_q/g_k/g_v (tf32-rounded)
    gemm_qkv<<<dim3(QKV_N / BN, (BATCH * SEQ) / BM), 256, GEMM_SMEM_BYTES>>>(
        x, w_qkv, b_qkv);

    // 2) causal flash attention -> g_o
    flash_attn<<<dim3(SEQ / FBR, NH, BATCH), 256, FLASH_SMEM_BYTES>>>();

    // 3) out = attn @ w_out^T (A read straight from g_o layout)
    gemm_proj<<<dim3(CH / BN, (BATCH * SEQ) / BM), 256, GEMM_SMEM_BYTES>>>(
        w_out, out);

    // 4) + b_out
    bias_add<<<(BATCH * SEQ * CH / 4) / 256, 256>>>(out, b_out);
}